// round 3
// baseline (speedup 1.0000x reference)
#include <cuda_runtime.h>

// ConformerAttention: B=8, S=1024, D=512, H=8, hd=64, P=2047
// rel_shift identity: shifted[i,j] = raw[i, j + (S-1) - i] -> p row r = 1023 + j - i.

#define CB 8
#define CS 1024
#define CD 512
#define CH 8
#define CHD 64
#define CP 2047
#define MTOK (CB*CS)   // 8192

typedef unsigned long long u64;

__device__ __forceinline__ u64 ffma2(u64 a, u64 b, u64 c) {
    u64 d; asm("fma.rn.f32x2 %0, %1, %2, %3;" : "=l"(d) : "l"(a), "l"(b), "l"(c)); return d;
}
__device__ __forceinline__ u64 fadd2(u64 a, u64 b) {
    u64 d; asm("add.rn.f32x2 %0, %1, %2;" : "=l"(d) : "l"(a), "l"(b)); return d;
}
__device__ __forceinline__ u64 dup2(float x) {
    u64 d; unsigned xi = __float_as_uint(x);
    asm("mov.b64 %0, {%1, %2};" : "=l"(d) : "r"(xi), "r"(xi)); return d;
}
__device__ __forceinline__ float2 unpk(u64 v) {
    float2 f; asm("mov.b64 {%0, %1}, %2;" : "=f"(f.x), "=f"(f.y) : "l"(v)); return f;
}

// -------- scratch (allocation-free: device globals) --------
__device__ float g_h [MTOK*CD];
__device__ float g_q [CB*CH*CS*CHD];
__device__ float g_k [CB*CH*CS*CHD];
__device__ float g_v [CB*CH*CS*CHD];
__device__ float g_p [CH*CP*CHD];
__device__ float g_ao[MTOK*CD];

// ============================ LayerNorm ============================
__global__ void __launch_bounds__(128) ln_kernel(const float* __restrict__ x,
    const float* __restrict__ w, const float* __restrict__ b, float* __restrict__ out)
{
    int row = blockIdx.x;
    int t = threadIdx.x;
    const float* xr = x + (size_t)row * CD;
    float4 v = *(const float4*)(xr + t * 4);
    float s = v.x + v.y + v.z + v.w;
    #pragma unroll
    for (int o = 16; o; o >>= 1) s += __shfl_xor_sync(0xffffffffu, s, o);
    __shared__ float ws1[4], ws2[4];
    if ((t & 31) == 0) ws1[t >> 5] = s;
    __syncthreads();
    float mean = (ws1[0] + ws1[1] + ws1[2] + ws1[3]) * (1.0f / 512.0f);
    float dx = v.x - mean, dy = v.y - mean, dz = v.z - mean, dw = v.w - mean;
    float q = dx*dx + dy*dy + dz*dz + dw*dw;
    #pragma unroll
    for (int o = 16; o; o >>= 1) q += __shfl_xor_sync(0xffffffffu, q, o);
    if ((t & 31) == 0) ws2[t >> 5] = q;
    __syncthreads();
    float var = (ws2[0] + ws2[1] + ws2[2] + ws2[3]) * (1.0f / 512.0f);
    float rstd = rsqrtf(var + 1e-5f);
    float4 wv = *(const float4*)(w + t * 4);
    float4 bv = *(const float4*)(b + t * 4);
    float4 o4;
    o4.x = dx * rstd * wv.x + bv.x;
    o4.y = dy * rstd * wv.y + bv.y;
    o4.z = dz * rstd * wv.z + bv.z;
    o4.w = dw * rstd * wv.w + bv.w;
    *(float4*)(out + (size_t)row * CD + t * 4) = o4;
}

// ============================ GEMM: C = A @ W^T (FFMA2) ============================
// Tile 128x128, 256 threads, 8x8 micro with f32x2-packed column pairs.
// A: [M, 512] row-major, W: [512, 512] row-major.
__global__ void __launch_bounds__(256, 2) gemm_kernel(
    const float* __restrict__ A, int M,
    const float* __restrict__ W,
    const float* __restrict__ bias,
    const float* __restrict__ resid,
    float* __restrict__ out, int mode)
{
    __shared__ float As[16 * 132];   // [k][m]
    __shared__ float Ws[16 * 132];   // [k][n]
    const int tid = threadIdx.x;
    const int m0 = blockIdx.y * 128, n0 = blockIdx.x * 128;
    const int rg = tid >> 4, cg = tid & 15;

    // staging assignment: threads 0-127 transpose A, 128-255 transpose W
    const int sb = tid & 127;
    const bool isA = tid < 128;
    const int rb = (sb & 31) * 4, kb = (sb >> 5) * 4;
    const float* src = isA ? A : W;
    const int rowbase = (isA ? m0 : n0) + rb;
    float* dst = isA ? As : Ws;

    u64 acc[8][4];
    #pragma unroll
    for (int t = 0; t < 8; t++)
        #pragma unroll
        for (int p = 0; p < 4; p++) acc[t][p] = 0ULL;

    for (int k0 = 0; k0 < 512; k0 += 16) {
        __syncthreads();
        float rr[4][4];
        #pragma unroll
        for (int i = 0; i < 4; i++) {
            int r = rowbase + i;
            float4 v = (isA && r >= M) ? make_float4(0.f,0.f,0.f,0.f)
                                       : *(const float4*)(src + (size_t)r * 512 + k0 + kb);
            rr[i][0] = v.x; rr[i][1] = v.y; rr[i][2] = v.z; rr[i][3] = v.w;
        }
        #pragma unroll
        for (int j = 0; j < 4; j++)
            *(float4*)&dst[(kb + j) * 132 + rb] = make_float4(rr[0][j], rr[1][j], rr[2][j], rr[3][j]);
        __syncthreads();

        #pragma unroll
        for (int kk = 0; kk < 16; kk++) {
            float4 a0 = *(const float4*)&As[kk * 132 + rg * 8];
            float4 a1 = *(const float4*)&As[kk * 132 + rg * 8 + 4];
            float af[8] = {a0.x,a0.y,a0.z,a0.w,a1.x,a1.y,a1.z,a1.w};
            u64 bp[4];
            #pragma unroll
            for (int p = 0; p < 4; p++)
                bp[p] = *(const u64*)&Ws[kk * 132 + cg * 2 + 32 * p];
            #pragma unroll
            for (int t = 0; t < 8; t++) {
                u64 ad = dup2(af[t]);
                #pragma unroll
                for (int p = 0; p < 4; p++) acc[t][p] = ffma2(ad, bp[p], acc[t][p]);
            }
        }
    }

    #pragma unroll
    for (int t = 0; t < 8; t++) {
        int m = m0 + rg * 8 + t;
        #pragma unroll
        for (int p = 0; p < 4; p++) {
            float2 f = unpk(acc[t][p]);
            int n = n0 + cg * 2 + 32 * p;
            if (mode == 0) {
                int bi = m >> 10, sr = m & 1023;
                float* o = out + ((size_t)(bi * CH + (n >> 6)) << 16) + ((size_t)sr << 6);
                o[n & 63]       = f.x + bias[n];
                o[(n & 63) + 1] = f.y + bias[n + 1];
            } else if (mode == 3) {
                if (m < M) {
                    float* o = out + ((size_t)(n >> 6) * CP + m) * 64 + (n & 63);
                    o[0] = f.x; o[1] = f.y;
                }
            } else {
                size_t idx = (size_t)m * 512 + n;
                out[idx]     = f.x + bias[n]     + resid[idx];
                out[idx + 1] = f.y + bias[n + 1] + resid[idx + 1];
            }
        }
    }
}

// ============================ Fused attention (FFMA2) ============================
constexpr int SC_STR  = 1032;
constexpr int SC_F    = 32 * SC_STR;      // 33024
constexpr int QT_F    = 64 * 36;          // 2304
constexpr int KB_STR  = 544;
constexpr int KBUF_F  = 32 * KB_STR;      // 17408 (also: V chunk 128*68=8704; partials 8*2176=17408)
constexpr int ASM_F   = SC_F + 2 * QT_F + KBUF_F;
constexpr int ASM_B   = ASM_F * 4;        // 220160 bytes

// stage 512 rows x 32 d (transposed) into kbuf[d][col], stride KB_STR
__device__ __forceinline__ void stage_kbuf(float* kbuf, const float* __restrict__ src,
                                           int rbase, int doff, int rowmax, int tid)
{
    #pragma unroll
    for (int it = 0; it < 4; it++) {
        int blk = tid + it * 256;
        int c0 = (blk & 127) * 4;
        int d0 = (blk >> 7) * 4;
        float rr[4][4];
        #pragma unroll
        for (int i = 0; i < 4; i++) {
            int row = rbase + c0 + i;
            float4 v = (row < rowmax) ? *(const float4*)(src + (size_t)row * 64 + doff + d0)
                                      : make_float4(0.f,0.f,0.f,0.f);
            rr[i][0] = v.x; rr[i][1] = v.y; rr[i][2] = v.z; rr[i][3] = v.w;
        }
        #pragma unroll
        for (int j = 0; j < 4; j++)
            *(float4*)&kbuf[(d0 + j) * KB_STR + c0] = make_float4(rr[0][j], rr[1][j], rr[2][j], rr[3][j]);
    }
}

__device__ __forceinline__ void computeB(const float* qt, const float* kbuf,
                                         int doff, int rg, int cg, u64 acc[8][4])
{
    #pragma unroll 4
    for (int k = 0; k < 32; k++) {
        const float* qrow = qt + (doff + k) * 36;
        float4 a0 = *(const float4*)&qrow[rg * 8];
        float4 a1 = *(const float4*)&qrow[rg * 8 + 4];
        float af[8] = {a0.x,a0.y,a0.z,a0.w,a1.x,a1.y,a1.z,a1.w};
        u64 bp[4];
        #pragma unroll
        for (int p = 0; p < 4; p++)
            bp[p] = *(const u64*)&kbuf[k * KB_STR + cg * 2 + 128 * p];
        #pragma unroll
        for (int t = 0; t < 8; t++) {
            u64 ad = dup2(af[t]);
            #pragma unroll
            for (int p = 0; p < 4; p++) acc[t][p] = ffma2(ad, bp[p], acc[t][p]);
        }
    }
}

__global__ void __launch_bounds__(256, 1) attn_kernel(const float* __restrict__ bu,
    const float* __restrict__ bvp, float* __restrict__ ao)
{
    extern __shared__ float sm[];
    float* sc   = sm;                 // [32][1032]
    float* qut  = sm + SC_F;          // [64][36]  (q + bias_u)^T
    float* qvt  = qut + QT_F;         // [64][36]  (q + bias_v)^T
    float* kbuf = qvt + QT_F;

    const int tid = threadIdx.x;
    const int w = tid >> 5, l = tid & 31;
    const int qt = blockIdx.x & 31;
    const int bh = blockIdx.x >> 5;
    const int h  = bh & 7, b = bh >> 3;
    const int i0 = qt * 32;
    const float* qbase = g_q + (size_t)bh * (CS * CHD);
    const float* kbase = g_k + (size_t)bh * (CS * CHD);
    const float* vbase = g_v + (size_t)bh * (CS * CHD);
    const float* pbase = g_p + (size_t)h  * (CP * CHD);

    // ---- Phase A: q tile transposed, both bias variants ----
    {
        int ii = tid & 31, dgb = tid >> 5;
        #pragma unroll
        for (int it = 0; it < 2; it++) {
            int d4 = dgb + it * 8;
            float4 qv = *(const float4*)(qbase + (size_t)(i0 + ii) * 64 + d4 * 4);
            float uq[4] = {qv.x, qv.y, qv.z, qv.w};
            #pragma unroll
            for (int t = 0; t < 4; t++) {
                int d = d4 * 4 + t;
                qut[d * 36 + ii] = uq[t] + bu [h * 64 + d];
                qvt[d * 36 + ii] = uq[t] + bvp[h * 64 + d];
            }
        }
    }

    const int rg = tid >> 6;       // 4 row-groups of 8
    const int cg = tid & 63;       // 64 col-groups (pairs at cg*2 + 128p)

    // ---- Phase B1: pos scores, sheared scatter (assign) ----
    const int rlo = 992 - i0;
    const int rbases[3] = {rlo, rlo + 512, rlo + 543};
    #pragma unroll 1
    for (int c = 0; c < 3; c++) {
        int rbase = rbases[c];
        u64 acc[8][4];
        #pragma unroll
        for (int t = 0; t < 8; t++)
            #pragma unroll
            for (int p = 0; p < 4; p++) acc[t][p] = 0ULL;
        #pragma unroll
        for (int half = 0; half < 2; half++) {
            __syncthreads();
            stage_kbuf(kbuf, pbase, rbase, half * 32, 2047, tid);
            __syncthreads();
            computeB(qvt, kbuf, half * 32, rg, cg, acc);
        }
        #pragma unroll
        for (int t = 0; t < 8; t++) {
            int ii = rg * 8 + t;
            int jc = rbase + i0 + ii - 1023 + cg * 2;
            #pragma unroll
            for (int p = 0; p < 4; p++) {
                float2 f = unpk(acc[t][p]);
                int j = jc + 128 * p;
                if (j >= 0 && j < 1024)         sc[ii * SC_STR + j]     = f.x;
                if (j + 1 >= 0 && j + 1 < 1024) sc[ii * SC_STR + j + 1] = f.y;
            }
        }
    }

    // ---- Phase B2: content scores (add in place) ----
    #pragma unroll 1
    for (int cc = 0; cc < 2; cc++) {
        int base = cc * 512;
        u64 acc[8][4];
        #pragma unroll
        for (int t = 0; t < 8; t++)
            #pragma unroll
            for (int p = 0; p < 4; p++) acc[t][p] = 0ULL;
        #pragma unroll
        for (int half = 0; half < 2; half++) {
            __syncthreads();
            stage_kbuf(kbuf, kbase, base, half * 32, 1024, tid);
            __syncthreads();
            computeB(qut, kbuf, half * 32, rg, cg, acc);
        }
        #pragma unroll
        for (int t = 0; t < 8; t++) {
            int ii = rg * 8 + t;
            #pragma unroll
            for (int p = 0; p < 4; p++) {
                int idx = ii * SC_STR + base + cg * 2 + 128 * p;
                u64 old = *(const u64*)&sc[idx];
                *(u64*)&sc[idx] = fadd2(acc[t][p], old);
            }
        }
    }
    __syncthreads();

    // ---- Phase C: softmax (scale 1/8 inside exp) ----
    #pragma unroll
    for (int rr = 0; rr < 4; rr++) {
        int row = w * 4 + rr;
        float* rp = sc + row * SC_STR;
        float4 vv[8];
        float mx = -1e30f;
        #pragma unroll
        for (int g = 0; g < 8; g++) {
            vv[g] = *(const float4*)&rp[g * 128 + l * 4];
            mx = fmaxf(mx, fmaxf(fmaxf(vv[g].x, vv[g].y), fmaxf(vv[g].z, vv[g].w)));
        }
        #pragma unroll
        for (int o = 16; o; o >>= 1) mx = fmaxf(mx, __shfl_xor_sync(0xffffffffu, mx, o));
        float sum = 0.f;
        #pragma unroll
        for (int g = 0; g < 8; g++) {
            vv[g].x = __expf((vv[g].x - mx) * 0.125f);
            vv[g].y = __expf((vv[g].y - mx) * 0.125f);
            vv[g].z = __expf((vv[g].z - mx) * 0.125f);
            vv[g].w = __expf((vv[g].w - mx) * 0.125f);
            sum += vv[g].x + vv[g].y + vv[g].z + vv[g].w;
        }
        #pragma unroll
        for (int o = 16; o; o >>= 1) sum += __shfl_xor_sync(0xffffffffu, sum, o);
        float inv = 1.0f / sum;
        #pragma unroll
        for (int g = 0; g < 8; g++) {
            vv[g].x *= inv; vv[g].y *= inv; vv[g].z *= inv; vv[g].w *= inv;
            *(float4*)&rp[g * 128 + l * 4] = vv[g];
        }
    }

    // ---- Phase D: O = attn @ V, 8-way k-split, FFMA2 ----
    const int dg = (l & 7) * 2;          // col-pair base (pairs at dg + 16p)
    const int rgd = l >> 3;              // rows rgd + 4t
    u64 oacc[8][4];
    #pragma unroll
    for (int t = 0; t < 8; t++)
        #pragma unroll
        for (int p = 0; p < 4; p++) oacc[t][p] = 0ULL;

    #pragma unroll 1
    for (int ch = 0; ch < 8; ch++) {
        __syncthreads();
        #pragma unroll
        for (int it = 0; it < 8; it++) {
            int e = tid + it * 256;          // float4 id 0..2047
            int key = e >> 4, dd = (e & 15) * 4;
            *(float4*)&kbuf[key * 68 + dd] =
                *(const float4*)(vbase + (size_t)(ch * 128 + key) * 64 + dd);
        }
        __syncthreads();
        int kb = w * 16;
        #pragma unroll
        for (int kk4 = 0; kk4 < 4; kk4++) {
            float4 a4[8];
            #pragma unroll
            for (int t = 0; t < 8; t++)
                a4[t] = *(const float4*)&sc[(rgd + 4 * t) * SC_STR + ch * 128 + kb + kk4 * 4];
            #pragma unroll
            for (int q = 0; q < 4; q++) {
                int klocal = kb + kk4 * 4 + q;
                u64 vp[4];
                #pragma unroll
                for (int p = 0; p < 4; p++)
                    vp[p] = *(const u64*)&kbuf[klocal * 68 + dg + 16 * p];
                #pragma unroll
                for (int t = 0; t < 8; t++) {
                    float av = (q == 0) ? a4[t].x : (q == 1) ? a4[t].y : (q == 2) ? a4[t].z : a4[t].w;
                    u64 ad = dup2(av);
                    #pragma unroll
                    for (int p = 0; p < 4; p++) oacc[t][p] = ffma2(ad, vp[p], oacc[t][p]);
                }
            }
        }
    }

    // per-warp partials -> kbuf, then cross-warp reduce
    __syncthreads();
    #pragma unroll
    for (int t = 0; t < 8; t++) {
        int row = rgd + 4 * t;
        #pragma unroll
        for (int p = 0; p < 4; p++)
            *(u64*)&kbuf[w * 2176 + row * 68 + dg + 16 * p] = oacc[t][p];
    }
    __syncthreads();
    #pragma unroll
    for (int rep = 0; rep < 2; rep++) {
        int e = tid + rep * 256;          // float4 id 0..511
        int row = e >> 4, d4 = (e & 15) * 4;
        float4 s = make_float4(0.f, 0.f, 0.f, 0.f);
        #pragma unroll
        for (int ww = 0; ww < 8; ww++) {
            float4 p4 = *(const float4*)&kbuf[ww * 2176 + row * 68 + d4];
            s.x += p4.x; s.y += p4.y; s.z += p4.z; s.w += p4.w;
        }
        *(float4*)&ao[(size_t)(b * 1024 + i0 + row) * 512 + h * 64 + d4] = s;
    }
}

// ============================ launch ============================
extern "C" void kernel_launch(void* const* d_in, const int* in_sizes, int n_in,
                              void* d_out, int out_size)
{
    const float* x       = (const float*)d_in[0];
    const float* pos_emb = (const float*)d_in[1];
    const float* ln_w    = (const float*)d_in[2];
    const float* ln_b    = (const float*)d_in[3];
    const float* Wq      = (const float*)d_in[4];
    const float* bq      = (const float*)d_in[5];
    const float* Wk      = (const float*)d_in[6];
    const float* bk      = (const float*)d_in[7];
    const float* Wv      = (const float*)d_in[8];
    const float* bv      = (const float*)d_in[9];
    const float* Wo      = (const float*)d_in[10];
    const float* bo      = (const float*)d_in[11];
    const float* Wp      = (const float*)d_in[12];
    const float* pbu     = (const float*)d_in[13];
    const float* pbv     = (const float*)d_in[14];
    float* out = (float*)d_out;

    float *hp, *qp, *kp, *vp, *pp, *aop;
    cudaGetSymbolAddress((void**)&hp,  g_h);
    cudaGetSymbolAddress((void**)&qp,  g_q);
    cudaGetSymbolAddress((void**)&kp,  g_k);
    cudaGetSymbolAddress((void**)&vp,  g_v);
    cudaGetSymbolAddress((void**)&pp,  g_p);
    cudaGetSymbolAddress((void**)&aop, g_ao);

    cudaFuncSetAttribute(attn_kernel, cudaFuncAttributeMaxDynamicSharedMemorySize, ASM_B);

    ln_kernel<<<MTOK, 128>>>(x, ln_w, ln_b, hp);

    gemm_kernel<<<dim3(4, 64), 256>>>(hp, MTOK, Wq, bq, nullptr, qp, 0);
    gemm_kernel<<<dim3(4, 64), 256>>>(hp, MTOK, Wk, bk, nullptr, kp, 0);
    gemm_kernel<<<dim3(4, 64), 256>>>(hp, MTOK, Wv, bv, nullptr, vp, 0);
    gemm_kernel<<<dim3(4, 16), 256>>>(pos_emb, CP, Wp, nullptr, nullptr, pp, 3);

    attn_kernel<<<CB * CH * (CS / 32), 256, ASM_B>>>(pbu, pbv, aop);

    gemm_kernel<<<dim3(4, 64), 256>>>(aop, MTOK, Wo, bo, x, out, 4);
}

// round 4
// speedup vs baseline: 2.1531x; 2.1531x over previous
#include <cuda_runtime.h>

// ConformerAttention: B=8, S=1024, D=512, H=8, hd=64, P=2047
// rel_shift identity: shifted[i,j] = raw[i, j + (S-1) - i] -> p row r = 1023 + j - i.
// With rlo = 992 - i0:  j = rr + ii - 31  (rr = band-local column).

#define CB 8
#define CS 1024
#define CD 512
#define CH 8
#define CHD 64
#define CP 2047
#define MTOK (CB*CS)   // 8192

__device__ __forceinline__ unsigned f2tf(float x) {
    unsigned r; asm("cvt.rna.tf32.f32 %0, %1;" : "=r"(r) : "f"(x)); return r;
}
__device__ __forceinline__ float f2tf_f(float x) { return __uint_as_float(f2tf(x)); }

__device__ __forceinline__ void mma8(float4& c, unsigned a0, unsigned a1, unsigned a2, unsigned a3,
                                     unsigned b0, unsigned b1) {
    asm volatile(
        "mma.sync.aligned.m16n8k8.row.col.f32.tf32.tf32.f32 "
        "{%0,%1,%2,%3}, {%4,%5,%6,%7}, {%8,%9}, {%0,%1,%2,%3};"
        : "+f"(c.x), "+f"(c.y), "+f"(c.z), "+f"(c.w)
        : "r"(a0), "r"(a1), "r"(a2), "r"(a3), "r"(b0), "r"(b1));
}

// -------- scratch (allocation-free: device globals) --------
__device__ float g_h [MTOK*CD];
__device__ float g_q [CB*CH*CS*CHD];
__device__ float g_k [CB*CH*CS*CHD];
__device__ float g_v [CB*CH*CS*CHD];
__device__ float g_p [CH*CP*CHD];
__device__ float g_ao[MTOK*CD];

// ============================ LayerNorm ============================
__global__ void __launch_bounds__(128) ln_kernel(const float* __restrict__ x,
    const float* __restrict__ w, const float* __restrict__ b, float* __restrict__ out)
{
    int row = blockIdx.x;
    int t = threadIdx.x;
    const float* xr = x + (size_t)row * CD;
    float4 v = *(const float4*)(xr + t * 4);
    float s = v.x + v.y + v.z + v.w;
    #pragma unroll
    for (int o = 16; o; o >>= 1) s += __shfl_xor_sync(0xffffffffu, s, o);
    __shared__ float ws1[4], ws2[4];
    if ((t & 31) == 0) ws1[t >> 5] = s;
    __syncthreads();
    float mean = (ws1[0] + ws1[1] + ws1[2] + ws1[3]) * (1.0f / 512.0f);
    float dx = v.x - mean, dy = v.y - mean, dz = v.z - mean, dw = v.w - mean;
    float q = dx*dx + dy*dy + dz*dz + dw*dw;
    #pragma unroll
    for (int o = 16; o; o >>= 1) q += __shfl_xor_sync(0xffffffffu, q, o);
    if ((t & 31) == 0) ws2[t >> 5] = q;
    __syncthreads();
    float var = (ws2[0] + ws2[1] + ws2[2] + ws2[3]) * (1.0f / 512.0f);
    float rstd = rsqrtf(var + 1e-5f);
    float4 wv = *(const float4*)(w + t * 4);
    float4 bv = *(const float4*)(b + t * 4);
    float4 o4;
    o4.x = dx * rstd * wv.x + bv.x;
    o4.y = dy * rstd * wv.y + bv.y;
    o4.z = dz * rstd * wv.z + bv.z;
    o4.w = dw * rstd * wv.w + bv.w;
    *(float4*)(out + (size_t)row * CD + t * 4) = o4;
}

// ============================ GEMM: C = A @ W^T (tf32 mma.sync) ============================
// Tile 128x128, 256 threads = 8 warps (4m x 2n), warp tile 32x64.
// A: [M, 512] row-major, W: [512, 512] row-major (W rows = col-major B columns).
__global__ void __launch_bounds__(256, 2) gemm_kernel(
    const float* __restrict__ A, int M,
    const float* __restrict__ W,
    const float* __restrict__ bias,
    const float* __restrict__ resid,
    float* __restrict__ out, int mode)
{
    __shared__ float As[128 * 36];   // [row][k], k-chunk 32, pad 4
    __shared__ float Ws[128 * 36];
    const int tid = threadIdx.x;
    const int l = tid & 31, wid = tid >> 5;
    const int wm = wid >> 1, wn = wid & 1;
    const int m0 = blockIdx.y * 128, n0 = blockIdx.x * 128;
    const int gid = l >> 2, tig = l & 3;    // groupID, thread-in-group

    float4 cacc[2][8];
    #pragma unroll
    for (int mt = 0; mt < 2; mt++)
        #pragma unroll
        for (int nt = 0; nt < 8; nt++) cacc[mt][nt] = make_float4(0.f, 0.f, 0.f, 0.f);

    for (int k0 = 0; k0 < 512; k0 += 32) {
        __syncthreads();
        #pragma unroll
        for (int it = 0; it < 4; it++) {
            int idx = tid + it * 256;        // 0..1023
            int row = idx >> 3, kk = (idx & 7) * 4;
            int am = m0 + row;
            float4 av = (am < M) ? *(const float4*)(A + (size_t)am * 512 + k0 + kk)
                                 : make_float4(0.f, 0.f, 0.f, 0.f);
            *(float4*)&As[row * 36 + kk] =
                make_float4(f2tf_f(av.x), f2tf_f(av.y), f2tf_f(av.z), f2tf_f(av.w));
            float4 wv = *(const float4*)(W + (size_t)(n0 + row) * 512 + k0 + kk);
            *(float4*)&Ws[row * 36 + kk] =
                make_float4(f2tf_f(wv.x), f2tf_f(wv.y), f2tf_f(wv.z), f2tf_f(wv.w));
        }
        __syncthreads();
        #pragma unroll
        for (int ks = 0; ks < 4; ks++) {
            int d0 = ks * 8 + tig;
            unsigned a[2][4];
            #pragma unroll
            for (int mt = 0; mt < 2; mt++) {
                const float* ar = As + (wm * 32 + mt * 16 + gid) * 36;
                a[mt][0] = __float_as_uint(ar[d0]);
                a[mt][1] = __float_as_uint(ar[8 * 36 + d0]);
                a[mt][2] = __float_as_uint(ar[d0 + 4]);
                a[mt][3] = __float_as_uint(ar[8 * 36 + d0 + 4]);
            }
            #pragma unroll
            for (int nt = 0; nt < 8; nt++) {
                const float* br = Ws + (wn * 64 + nt * 8 + gid) * 36;
                unsigned b0 = __float_as_uint(br[d0]);
                unsigned b1 = __float_as_uint(br[d0 + 4]);
                mma8(cacc[0][nt], a[0][0], a[0][1], a[0][2], a[0][3], b0, b1);
                mma8(cacc[1][nt], a[1][0], a[1][1], a[1][2], a[1][3], b0, b1);
            }
        }
    }

    #pragma unroll
    for (int mt = 0; mt < 2; mt++) {
        #pragma unroll
        for (int nt = 0; nt < 8; nt++) {
            float4 c = cacc[mt][nt];
            int r0 = m0 + wm * 32 + mt * 16 + gid;
            int c0 = n0 + wn * 64 + nt * 8 + tig * 2;
            float vals[4] = {c.x, c.y, c.z, c.w};
            #pragma unroll
            for (int e = 0; e < 4; e++) {
                int m = r0 + (e >= 2 ? 8 : 0);
                int n = c0 + (e & 1);
                float val = vals[e];
                if (mode == 0) {
                    int bi = m >> 10, sr = m & 1023;
                    out[((size_t)(bi * CH + (n >> 6)) << 16) + ((size_t)sr << 6) + (n & 63)]
                        = val + bias[n];
                } else if (mode == 3) {
                    if (m < M)
                        out[((size_t)(n >> 6) * CP + m) * 64 + (n & 63)] = val;
                } else {
                    size_t idx = (size_t)m * 512 + n;
                    out[idx] = val + bias[n] + resid[idx];
                }
            }
        }
    }
}

// ============================ Fused attention (tf32 mma.sync) ============================
constexpr int SC_STR = 1060;               // 1060 % 32 == 4 -> conflict-free frag loads
constexpr int SC_F   = 32 * SC_STR;        // 33920
constexpr int QT_F   = 32 * 68;            // 2176 each
constexpr int KBUF_F = 17408;              // Ksm 128*68=8704 | Vtsm 64*132=8448 | partials 8*2176
constexpr int ASM_F  = SC_F + 2 * QT_F + KBUF_F;   // 55680
constexpr int ASM_B  = ASM_F * 4;                  // 222720 bytes

// scores chunk: C[32 x 16(warp)] += At[32x64] @ Ks[128x64]^T slice, tf32 mma
__device__ __forceinline__ void mma_chunk(const float* __restrict__ At,
                                          const float* __restrict__ Ks,
                                          int w, int l, float4 cacc[2][2])
{
    const int gid = l >> 2, tig = l & 3;
    #pragma unroll
    for (int ks = 0; ks < 8; ks++) {
        int d0 = ks * 8 + tig;
        unsigned a[2][4];
        #pragma unroll
        for (int mt = 0; mt < 2; mt++) {
            const float* ar = At + (mt * 16 + gid) * 68;
            a[mt][0] = __float_as_uint(ar[d0]);
            a[mt][1] = __float_as_uint(ar[8 * 68 + d0]);
            a[mt][2] = __float_as_uint(ar[d0 + 4]);
            a[mt][3] = __float_as_uint(ar[8 * 68 + d0 + 4]);
        }
        #pragma unroll
        for (int nt = 0; nt < 2; nt++) {
            const float* br = Ks + (w * 16 + nt * 8 + gid) * 68;
            unsigned b0 = __float_as_uint(br[d0]);
            unsigned b1 = __float_as_uint(br[d0 + 4]);
            mma8(cacc[0][nt], a[0][0], a[0][1], a[0][2], a[0][3], b0, b1);
            mma8(cacc[1][nt], a[1][0], a[1][1], a[1][2], a[1][3], b0, b1);
        }
    }
}

__global__ void __launch_bounds__(256, 1) attn_kernel(const float* __restrict__ bu,
    const float* __restrict__ bvp, float* __restrict__ ao)
{
    extern __shared__ float sm[];
    float* sc   = sm;                 // [32][1060] fp32 scores / probabilities
    float* qut  = sm + SC_F;          // [32][68]  (q + bias_u), tf32 bits
    float* qvt  = qut + QT_F;         // [32][68]  (q + bias_v), tf32 bits
    float* kbuf = qvt + QT_F;         // staging / partials

    const int tid = threadIdx.x;
    const int w = tid >> 5, l = tid & 31;
    const int gid = l >> 2, tig = l & 3;
    const int qt = blockIdx.x & 31;
    const int bh = blockIdx.x >> 5;
    const int h  = bh & 7, b = bh >> 3;
    const int i0 = qt * 32;
    const float* qbase = g_q + (size_t)bh * (CS * CHD);
    const float* kbase = g_k + (size_t)bh * (CS * CHD);
    const float* vbase = g_v + (size_t)bh * (CS * CHD);
    const float* pbase = g_p + (size_t)h  * (CP * CHD);

    // ---- Phase A: q tile row-major [32][68], both bias variants, tf32 bits ----
    {
        int ii = tid >> 3;
        int d0 = (tid & 7) * 8;
        float4 q0 = *(const float4*)(qbase + (size_t)(i0 + ii) * 64 + d0);
        float4 q1 = *(const float4*)(qbase + (size_t)(i0 + ii) * 64 + d0 + 4);
        float qv[8] = {q0.x, q0.y, q0.z, q0.w, q1.x, q1.y, q1.z, q1.w};
        #pragma unroll
        for (int t = 0; t < 8; t++) {
            int d = d0 + t;
            qut[ii * 68 + d] = f2tf_f(qv[t] + bu [h * 64 + d]);
            qvt[ii * 68 + d] = f2tf_f(qv[t] + bvp[h * 64 + d]);
        }
    }

    const int rlo = 992 - i0;

    // ---- Phase B1: pos scores over band (9 chunks of 128), sheared assign ----
    #pragma unroll 1
    for (int ch = 0; ch < 9; ch++) {
        int rbase = rlo + ch * 128;
        __syncthreads();
        #pragma unroll
        for (int it = 0; it < 8; it++) {
            int e = tid + it * 256;
            int j = e >> 4, d4 = (e & 15) * 4;
            int r = rbase + j;
            float4 v = (r <= 2046) ? *(const float4*)(pbase + (size_t)r * 64 + d4)
                                   : make_float4(0.f, 0.f, 0.f, 0.f);
            *(float4*)&kbuf[j * 68 + d4] =
                make_float4(f2tf_f(v.x), f2tf_f(v.y), f2tf_f(v.z), f2tf_f(v.w));
        }
        __syncthreads();
        float4 cacc[2][2];
        #pragma unroll
        for (int mt = 0; mt < 2; mt++)
            #pragma unroll
            for (int nt = 0; nt < 2; nt++) cacc[mt][nt] = make_float4(0.f,0.f,0.f,0.f);
        mma_chunk(qvt, kbuf, w, l, cacc);
        #pragma unroll
        for (int mt = 0; mt < 2; mt++) {
            #pragma unroll
            for (int nt = 0; nt < 2; nt++) {
                float4 c = cacc[mt][nt];
                int ii = mt * 16 + gid;
                int rr = ch * 128 + w * 16 + nt * 8 + tig * 2;
                int jx = rr + ii - 31;                 // j = rr + ii - 31
                if (jx >= 0 && jx < 1024)         sc[ii * SC_STR + jx]         = c.x;
                if (jx + 1 >= 0 && jx + 1 < 1024) sc[ii * SC_STR + jx + 1]     = c.y;
                int jz = jx + 8, i2 = ii + 8;
                if (jz >= 0 && jz < 1024)         sc[i2 * SC_STR + jz]         = c.z;
                if (jz + 1 >= 0 && jz + 1 < 1024) sc[i2 * SC_STR + jz + 1]     = c.w;
            }
        }
    }

    // ---- Phase B2: content scores, add in place ----
    #pragma unroll 1
    for (int ch = 0; ch < 8; ch++) {
        __syncthreads();
        #pragma unroll
        for (int it = 0; it < 8; it++) {
            int e = tid + it * 256;
            int j = e >> 4, d4 = (e & 15) * 4;
            float4 v = *(const float4*)(kbase + (size_t)(ch * 128 + j) * 64 + d4);
            *(float4*)&kbuf[j * 68 + d4] =
                make_float4(f2tf_f(v.x), f2tf_f(v.y), f2tf_f(v.z), f2tf_f(v.w));
        }
        __syncthreads();
        float4 cacc[2][2];
        #pragma unroll
        for (int mt = 0; mt < 2; mt++)
            #pragma unroll
            for (int nt = 0; nt < 2; nt++) cacc[mt][nt] = make_float4(0.f,0.f,0.f,0.f);
        mma_chunk(qut, kbuf, w, l, cacc);
        #pragma unroll
        for (int mt = 0; mt < 2; mt++) {
            #pragma unroll
            for (int nt = 0; nt < 2; nt++) {
                float4 c = cacc[mt][nt];
                int ii = mt * 16 + gid;
                int col = ch * 128 + w * 16 + nt * 8 + tig * 2;
                sc[ii * SC_STR + col]           += c.x;
                sc[ii * SC_STR + col + 1]       += c.y;
                sc[(ii + 8) * SC_STR + col]     += c.z;
                sc[(ii + 8) * SC_STR + col + 1] += c.w;
            }
        }
    }
    __syncthreads();

    // ---- Phase C: softmax (scale 1/8 inside exp) ----
    #pragma unroll
    for (int rr = 0; rr < 4; rr++) {
        int row = w * 4 + rr;
        float* rp = sc + row * SC_STR;
        float4 vv[8];
        float mx = -1e30f;
        #pragma unroll
        for (int g = 0; g < 8; g++) {
            vv[g] = *(const float4*)&rp[g * 128 + l * 4];
            mx = fmaxf(mx, fmaxf(fmaxf(vv[g].x, vv[g].y), fmaxf(vv[g].z, vv[g].w)));
        }
        #pragma unroll
        for (int o = 16; o; o >>= 1) mx = fmaxf(mx, __shfl_xor_sync(0xffffffffu, mx, o));
        float sum = 0.f;
        #pragma unroll
        for (int g = 0; g < 8; g++) {
            vv[g].x = __expf((vv[g].x - mx) * 0.125f);
            vv[g].y = __expf((vv[g].y - mx) * 0.125f);
            vv[g].z = __expf((vv[g].z - mx) * 0.125f);
            vv[g].w = __expf((vv[g].w - mx) * 0.125f);
            sum += vv[g].x + vv[g].y + vv[g].z + vv[g].w;
        }
        #pragma unroll
        for (int o = 16; o; o >>= 1) sum += __shfl_xor_sync(0xffffffffu, sum, o);
        float inv = 1.0f / sum;
        #pragma unroll
        for (int g = 0; g < 8; g++) {
            vv[g].x *= inv; vv[g].y *= inv; vv[g].z *= inv; vv[g].w *= inv;
            *(float4*)&rp[g * 128 + l * 4] = vv[g];
        }
    }
    __syncthreads();

    // ---- Phase D: O = attn @ V (tf32 mma), k split across warps ----
    float4 oacc[2][8];
    #pragma unroll
    for (int mt = 0; mt < 2; mt++)
        #pragma unroll
        for (int nt = 0; nt < 8; nt++) oacc[mt][nt] = make_float4(0.f,0.f,0.f,0.f);

    #pragma unroll 1
    for (int ch = 0; ch < 8; ch++) {
        __syncthreads();
        #pragma unroll
        for (int it = 0; it < 8; it++) {
            int e = tid + it * 256;
            int key = e >> 4, d4 = (e & 15) * 4;
            float4 v = *(const float4*)(vbase + (size_t)(ch * 128 + key) * 64 + d4);
            kbuf[(d4 + 0) * 132 + key] = f2tf_f(v.x);
            kbuf[(d4 + 1) * 132 + key] = f2tf_f(v.y);
            kbuf[(d4 + 2) * 132 + key] = f2tf_f(v.z);
            kbuf[(d4 + 3) * 132 + key] = f2tf_f(v.w);
        }
        __syncthreads();
        #pragma unroll
        for (int ks = 0; ks < 2; ks++) {
            int kk = w * 16 + ks * 8 + tig;          // key index within chunk
            unsigned a[2][4];
            #pragma unroll
            for (int mt = 0; mt < 2; mt++) {
                int r = mt * 16 + gid;
                const float* sr0 = sc + r * SC_STR + ch * 128;
                const float* sr1 = sc + (r + 8) * SC_STR + ch * 128;
                a[mt][0] = f2tf(sr0[kk]);
                a[mt][1] = f2tf(sr1[kk]);
                a[mt][2] = f2tf(sr0[kk + 4]);
                a[mt][3] = f2tf(sr1[kk + 4]);
            }
            #pragma unroll
            for (int nt = 0; nt < 8; nt++) {
                const float* br = kbuf + (nt * 8 + gid) * 132 + w * 16 + ks * 8;
                unsigned b0 = __float_as_uint(br[tig]);
                unsigned b1 = __float_as_uint(br[tig + 4]);
                mma8(oacc[0][nt], a[0][0], a[0][1], a[0][2], a[0][3], b0, b1);
                mma8(oacc[1][nt], a[1][0], a[1][1], a[1][2], a[1][3], b0, b1);
            }
        }
    }

    // per-warp partials -> kbuf, then cross-warp reduce
    __syncthreads();
    #pragma unroll
    for (int mt = 0; mt < 2; mt++) {
        #pragma unroll
        for (int nt = 0; nt < 8; nt++) {
            float4 c = oacc[mt][nt];
            int r = mt * 16 + gid;
            int cc = nt * 8 + tig * 2;
            float* pb = kbuf + w * 2176;
            pb[r * 68 + cc]           = c.x;
            pb[r * 68 + cc + 1]       = c.y;
            pb[(r + 8) * 68 + cc]     = c.z;
            pb[(r + 8) * 68 + cc + 1] = c.w;
        }
    }
    __syncthreads();
    #pragma unroll
    for (int rep = 0; rep < 2; rep++) {
        int e = tid + rep * 256;
        int row = e >> 4, d4 = (e & 15) * 4;
        float4 s = make_float4(0.f, 0.f, 0.f, 0.f);
        #pragma unroll
        for (int ww = 0; ww < 8; ww++) {
            float4 p4 = *(const float4*)&kbuf[ww * 2176 + row * 68 + d4];
            s.x += p4.x; s.y += p4.y; s.z += p4.z; s.w += p4.w;
        }
        *(float4*)&ao[(size_t)(b * 1024 + i0 + row) * 512 + h * 64 + d4] = s;
    }
}

// ============================ launch ============================
extern "C" void kernel_launch(void* const* d_in, const int* in_sizes, int n_in,
                              void* d_out, int out_size)
{
    const float* x       = (const float*)d_in[0];
    const float* pos_emb = (const float*)d_in[1];
    const float* ln_w    = (const float*)d_in[2];
    const float* ln_b    = (const float*)d_in[3];
    const float* Wq      = (const float*)d_in[4];
    const float* bq      = (const float*)d_in[5];
    const float* Wk      = (const float*)d_in[6];
    const float* bk      = (const float*)d_in[7];
    const float* Wv      = (const float*)d_in[8];
    const float* bv      = (const float*)d_in[9];
    const float* Wo      = (const float*)d_in[10];
    const float* bo      = (const float*)d_in[11];
    const float* Wp      = (const float*)d_in[12];
    const float* pbu     = (const float*)d_in[13];
    const float* pbv     = (const float*)d_in[14];
    float* out = (float*)d_out;

    float *hp, *qp, *kp, *vp, *pp, *aop;
    cudaGetSymbolAddress((void**)&hp,  g_h);
    cudaGetSymbolAddress((void**)&qp,  g_q);
    cudaGetSymbolAddress((void**)&kp,  g_k);
    cudaGetSymbolAddress((void**)&vp,  g_v);
    cudaGetSymbolAddress((void**)&pp,  g_p);
    cudaGetSymbolAddress((void**)&aop, g_ao);

    cudaFuncSetAttribute(attn_kernel, cudaFuncAttributeMaxDynamicSharedMemorySize, ASM_B);

    ln_kernel<<<MTOK, 128>>>(x, ln_w, ln_b, hp);

    gemm_kernel<<<dim3(4, 64), 256>>>(hp, MTOK, Wq, bq, nullptr, qp, 0);
    gemm_kernel<<<dim3(4, 64), 256>>>(hp, MTOK, Wk, bk, nullptr, kp, 0);
    gemm_kernel<<<dim3(4, 64), 256>>>(hp, MTOK, Wv, bv, nullptr, vp, 0);
    gemm_kernel<<<dim3(4, 16), 256>>>(pos_emb, CP, Wp, nullptr, nullptr, pp, 3);

    attn_kernel<<<CB * CH * (CS / 32), 256, ASM_B>>>(pbu, pbv, aop);

    gemm_kernel<<<dim3(4, 64), 256>>>(aop, MTOK, Wo, bo, x, out, 4);
}

// round 5
// speedup vs baseline: 3.5266x; 1.6379x over previous
#include <cuda_runtime.h>
#include <cuda_bf16.h>

// ConformerAttention: B=8, S=1024, D=512, H=8, hd=64, P=2047
// rel_shift identity: shifted[i,j] = raw[i, j + (S-1) - i] -> p row r = 1023 + j - i.
// With rlo = 992 - i0:  j = rr + ii - 31  (rr = band-local column).

#define CB 8
#define CS 1024
#define CD 512
#define CH 8
#define CHD 64
#define CP 2047
#define MTOK (CB*CS)   // 8192

typedef __nv_bfloat16 bf16;
typedef __nv_bfloat162 bf162;

__device__ __forceinline__ unsigned pack_bf2(float lo, float hi) {
    unsigned r; asm("cvt.rn.bf16x2.f32 %0, %1, %2;" : "=r"(r) : "f"(hi), "f"(lo)); return r;
}
__device__ __forceinline__ void mma16(float4& c, unsigned a0, unsigned a1, unsigned a2, unsigned a3,
                                      unsigned b0, unsigned b1) {
    asm volatile(
        "mma.sync.aligned.m16n8k16.row.col.f32.bf16.bf16.f32 "
        "{%0,%1,%2,%3}, {%4,%5,%6,%7}, {%8,%9}, {%0,%1,%2,%3};"
        : "+f"(c.x), "+f"(c.y), "+f"(c.z), "+f"(c.w)
        : "r"(a0), "r"(a1), "r"(a2), "r"(a3), "r"(b0), "r"(b1));
}

// -------- scratch (allocation-free: device globals) --------
__device__ bf16 g_h [MTOK*CD];
__device__ bf16 g_q [CB*CH*CS*CHD];      // [bh][S][hd]
__device__ bf16 g_k [CB*CH*CS*CHD];      // [bh][S][hd]
__device__ bf16 g_v [CB*CH*CS*CHD];      // [bh][hd][S]  (pre-transposed, mode 5)
__device__ bf16 g_p [CH*CP*CHD];         // [H][P][hd]
__device__ bf16 g_ao[MTOK*CD];           // [B,S,D]

// ============================ LayerNorm (fp32 in -> bf16 out) ============================
__global__ void __launch_bounds__(128) ln_kernel(const float* __restrict__ x,
    const float* __restrict__ w, const float* __restrict__ b, bf16* __restrict__ out)
{
    int row = blockIdx.x;
    int t = threadIdx.x;
    const float* xr = x + (size_t)row * CD;
    float4 v = *(const float4*)(xr + t * 4);
    float s = v.x + v.y + v.z + v.w;
    #pragma unroll
    for (int o = 16; o; o >>= 1) s += __shfl_xor_sync(0xffffffffu, s, o);
    __shared__ float ws1[4], ws2[4];
    if ((t & 31) == 0) ws1[t >> 5] = s;
    __syncthreads();
    float mean = (ws1[0] + ws1[1] + ws1[2] + ws1[3]) * (1.0f / 512.0f);
    float dx = v.x - mean, dy = v.y - mean, dz = v.z - mean, dw = v.w - mean;
    float q = dx*dx + dy*dy + dz*dz + dw*dw;
    #pragma unroll
    for (int o = 16; o; o >>= 1) q += __shfl_xor_sync(0xffffffffu, q, o);
    if ((t & 31) == 0) ws2[t >> 5] = q;
    __syncthreads();
    float var = (ws2[0] + ws2[1] + ws2[2] + ws2[3]) * (1.0f / 512.0f);
    float rstd = rsqrtf(var + 1e-5f);
    float4 wv = *(const float4*)(w + t * 4);
    float4 bv = *(const float4*)(b + t * 4);
    float ox = dx * rstd * wv.x + bv.x;
    float oy = dy * rstd * wv.y + bv.y;
    float oz = dz * rstd * wv.z + bv.z;
    float ow = dw * rstd * wv.w + bv.w;
    uint2 o2 = make_uint2(pack_bf2(ox, oy), pack_bf2(oz, ow));
    *(uint2*)(out + (size_t)row * CD + t * 4) = o2;
}

// ============================ GEMM: C = A @ W^T (bf16 mma m16n8k16) ============================
// Tile 128x128, 8 warps (4m x 2n), warp tile 32x64, k-chunk 64.
// mode 0: bf16 out [bh][S][hd] (+bias); mode 3: bf16 out [H][P][hd];
// mode 5: bf16 out [bh][hd][S] (V transposed, +bias); mode 4: fp32 out +bias+resid.
__global__ void __launch_bounds__(256, 2) gemm_kernel(
    const void* __restrict__ Ap, int M, int a_bf16,
    const float* __restrict__ W,
    const float* __restrict__ bias,
    const float* __restrict__ resid,
    void* __restrict__ outp, int mode)
{
    __shared__ bf16 As[128 * 72];
    __shared__ bf16 Ws[128 * 72];
    const int tid = threadIdx.x;
    const int l = tid & 31, wid = tid >> 5;
    const int wm = wid >> 1, wn = wid & 1;
    const int m0 = blockIdx.y * 128, n0 = blockIdx.x * 128;
    const int gid = l >> 2, tig = l & 3;

    float4 cacc[2][8];
    #pragma unroll
    for (int mt = 0; mt < 2; mt++)
        #pragma unroll
        for (int nt = 0; nt < 8; nt++) cacc[mt][nt] = make_float4(0.f, 0.f, 0.f, 0.f);

    for (int k0 = 0; k0 < 512; k0 += 64) {
        __syncthreads();
        #pragma unroll
        for (int it = 0; it < 4; it++) {
            int idx = tid + it * 256;        // 0..1023
            int row = idx >> 3, seg = idx & 7;
            int kk = k0 + seg * 8;
            int am = m0 + row;
            uint4 aw = make_uint4(0, 0, 0, 0);
            if (am < M) {
                if (a_bf16) {
                    aw = *(const uint4*)((const bf16*)Ap + (size_t)am * 512 + kk);
                } else {
                    const float* ar = (const float*)Ap + (size_t)am * 512 + kk;
                    float4 f0 = *(const float4*)ar;
                    float4 f1 = *(const float4*)(ar + 4);
                    aw = make_uint4(pack_bf2(f0.x, f0.y), pack_bf2(f0.z, f0.w),
                                    pack_bf2(f1.x, f1.y), pack_bf2(f1.z, f1.w));
                }
            }
            *(uint4*)&As[row * 72 + seg * 8] = aw;
            const float* wr = W + (size_t)(n0 + row) * 512 + kk;
            float4 w0 = *(const float4*)wr;
            float4 w1 = *(const float4*)(wr + 4);
            *(uint4*)&Ws[row * 72 + seg * 8] =
                make_uint4(pack_bf2(w0.x, w0.y), pack_bf2(w0.z, w0.w),
                           pack_bf2(w1.x, w1.y), pack_bf2(w1.z, w1.w));
        }
        __syncthreads();
        #pragma unroll
        for (int ks = 0; ks < 4; ks++) {
            int kb = ks * 16 + 2 * tig;
            unsigned a[2][4];
            #pragma unroll
            for (int mt = 0; mt < 2; mt++) {
                const bf16* ar = As + (wm * 32 + mt * 16 + gid) * 72 + kb;
                const bf16* ar8 = ar + 8 * 72;
                a[mt][0] = *(const unsigned*)ar;
                a[mt][1] = *(const unsigned*)ar8;
                a[mt][2] = *(const unsigned*)(ar + 8);
                a[mt][3] = *(const unsigned*)(ar8 + 8);
            }
            #pragma unroll
            for (int nt = 0; nt < 8; nt++) {
                const bf16* br = Ws + (wn * 64 + nt * 8 + gid) * 72 + kb;
                unsigned b0 = *(const unsigned*)br;
                unsigned b1 = *(const unsigned*)(br + 8);
                mma16(cacc[0][nt], a[0][0], a[0][1], a[0][2], a[0][3], b0, b1);
                mma16(cacc[1][nt], a[1][0], a[1][1], a[1][2], a[1][3], b0, b1);
            }
        }
    }

    #pragma unroll
    for (int mt = 0; mt < 2; mt++) {
        #pragma unroll
        for (int nt = 0; nt < 8; nt++) {
            float4 c = cacc[mt][nt];
            int r0 = m0 + wm * 32 + mt * 16 + gid;
            int c0 = n0 + wn * 64 + nt * 8 + tig * 2;
            float vals[4] = {c.x, c.y, c.z, c.w};
            #pragma unroll
            for (int e = 0; e < 4; e++) {
                int m = r0 + (e >= 2 ? 8 : 0);
                int n = c0 + (e & 1);
                float val = vals[e];
                if (mode == 0) {
                    int bi = m >> 10, sr = m & 1023;
                    ((bf16*)outp)[((size_t)(bi * CH + (n >> 6)) << 16) + ((size_t)sr << 6) + (n & 63)]
                        = __float2bfloat16(val + bias[n]);
                } else if (mode == 5) {
                    int bi = m >> 10, sr = m & 1023;
                    ((bf16*)outp)[((size_t)(bi * CH + (n >> 6)) << 16) + (size_t)(n & 63) * 1024 + sr]
                        = __float2bfloat16(val + bias[n]);
                } else if (mode == 3) {
                    if (m < M)
                        ((bf16*)outp)[((size_t)(n >> 6) * CP + m) * 64 + (n & 63)]
                            = __float2bfloat16(val);
                } else {
                    size_t idx = (size_t)m * 512 + n;
                    ((float*)outp)[idx] = val + bias[n] + resid[idx];
                }
            }
        }
    }
}

// ============================ Fused attention (bf16 mma) ============================
constexpr int SC_STR = 1060;
constexpr int SC_F   = 32 * SC_STR;            // fp32 scores (also AV partials overlay)
constexpr int QT_E   = 32 * 72;                // bf16 q tiles
constexpr int KB_E   = 128 * 72;               // bf16 K/P chunk (Vt 64*136=8704 fits)
constexpr int ASM_B  = SC_F * 4 + 2 * QT_E * 2 + KB_E * 2;   // 163,328 bytes

// scores chunk: C[32 x 16(warp)] += At[32x64] @ Ks[128x64]^T slice
__device__ __forceinline__ void mma_chunk(const bf16* __restrict__ At,
                                          const bf16* __restrict__ Ks,
                                          int w, int gid, int tig, float4 cacc[2][2])
{
    #pragma unroll
    for (int ks = 0; ks < 4; ks++) {
        int kb = ks * 16 + 2 * tig;
        unsigned a[2][4];
        #pragma unroll
        for (int mt = 0; mt < 2; mt++) {
            const bf16* ar = At + (mt * 16 + gid) * 72 + kb;
            const bf16* ar8 = ar + 8 * 72;
            a[mt][0] = *(const unsigned*)ar;
            a[mt][1] = *(const unsigned*)ar8;
            a[mt][2] = *(const unsigned*)(ar + 8);
            a[mt][3] = *(const unsigned*)(ar8 + 8);
        }
        #pragma unroll
        for (int nt = 0; nt < 2; nt++) {
            const bf16* br = Ks + (w * 16 + nt * 8 + gid) * 72 + kb;
            unsigned b0 = *(const unsigned*)br;
            unsigned b1 = *(const unsigned*)(br + 8);
            mma16(cacc[0][nt], a[0][0], a[0][1], a[0][2], a[0][3], b0, b1);
            mma16(cacc[1][nt], a[1][0], a[1][1], a[1][2], a[1][3], b0, b1);
        }
    }
}

__global__ void __launch_bounds__(256, 1) attn_kernel(const float* __restrict__ bu,
    const float* __restrict__ bvp, bf16* __restrict__ ao)
{
    extern __shared__ float sm[];
    float* sc  = sm;                                   // [32][1060] fp32
    bf16* qut  = (bf16*)(sm + SC_F);                   // [32][72]
    bf16* qvt  = qut + QT_E;                           // [32][72]
    bf16* kbuf = qvt + QT_E;                           // [128][72] / Vt [64][136]

    const int tid = threadIdx.x;
    const int w = tid >> 5, l = tid & 31;
    const int gid = l >> 2, tig = l & 3;
    const int qt = blockIdx.x & 31;
    const int bh = blockIdx.x >> 5;
    const int h  = bh & 7, b = bh >> 3;
    const int i0 = qt * 32;
    const bf16* qbase = g_q + (size_t)bh * (CS * CHD);
    const bf16* kbase = g_k + (size_t)bh * (CS * CHD);
    const bf16* vbase = g_v + (size_t)bh * (CS * CHD);   // [64][1024]
    const bf16* pbase = g_p + (size_t)h  * (CP * CHD);

    // ---- Phase A: q tile [32][72] bf16, both bias variants ----
    {
        int ii = tid >> 3, d0 = (tid & 7) * 8;
        uint4 qw = *(const uint4*)(qbase + (size_t)(i0 + ii) * 64 + d0);
        unsigned wsv[4] = {qw.x, qw.y, qw.z, qw.w};
        float qv[8];
        #pragma unroll
        for (int j = 0; j < 4; j++) {
            float2 f = __bfloat1622float2(*(bf162*)&wsv[j]);
            qv[2*j] = f.x; qv[2*j+1] = f.y;
        }
        unsigned uo[4], vo[4];
        #pragma unroll
        for (int j = 0; j < 4; j++) {
            int d = d0 + 2 * j;
            uo[j] = pack_bf2(qv[2*j] + bu [h*64+d], qv[2*j+1] + bu [h*64+d+1]);
            vo[j] = pack_bf2(qv[2*j] + bvp[h*64+d], qv[2*j+1] + bvp[h*64+d+1]);
        }
        *(uint4*)&qut[ii * 72 + d0] = make_uint4(uo[0], uo[1], uo[2], uo[3]);
        *(uint4*)&qvt[ii * 72 + d0] = make_uint4(vo[0], vo[1], vo[2], vo[3]);
    }

    const int rlo = 992 - i0;

    // ---- Phase B1: pos scores over band (9 chunks of 128), sheared assign ----
    #pragma unroll 1
    for (int ch = 0; ch < 9; ch++) {
        int rbase = rlo + ch * 128;
        __syncthreads();
        #pragma unroll
        for (int it = 0; it < 4; it++) {
            int idx = tid + it * 256;
            int row = idx >> 3, seg = idx & 7;
            int r = rbase + row;
            uint4 v = (r <= 2046) ? *(const uint4*)(pbase + (size_t)r * 64 + seg * 8)
                                  : make_uint4(0, 0, 0, 0);
            *(uint4*)&kbuf[row * 72 + seg * 8] = v;
        }
        __syncthreads();
        float4 cacc[2][2];
        #pragma unroll
        for (int mt = 0; mt < 2; mt++)
            #pragma unroll
            for (int nt = 0; nt < 2; nt++) cacc[mt][nt] = make_float4(0.f,0.f,0.f,0.f);
        mma_chunk(qvt, kbuf, w, gid, tig, cacc);
        #pragma unroll
        for (int mt = 0; mt < 2; mt++) {
            #pragma unroll
            for (int nt = 0; nt < 2; nt++) {
                float4 c = cacc[mt][nt];
                int ii = mt * 16 + gid;
                int rr = ch * 128 + w * 16 + nt * 8 + tig * 2;
                int jx = rr + ii - 31;
                if (jx >= 0 && jx < 1024)         sc[ii * SC_STR + jx]     = c.x;
                if (jx + 1 >= 0 && jx + 1 < 1024) sc[ii * SC_STR + jx + 1] = c.y;
                int jz = jx + 8, i2 = ii + 8;
                if (jz >= 0 && jz < 1024)         sc[i2 * SC_STR + jz]     = c.z;
                if (jz + 1 >= 0 && jz + 1 < 1024) sc[i2 * SC_STR + jz + 1] = c.w;
            }
        }
    }

    // ---- Phase B2: content scores, add in place ----
    #pragma unroll 1
    for (int ch = 0; ch < 8; ch++) {
        __syncthreads();
        #pragma unroll
        for (int it = 0; it < 4; it++) {
            int idx = tid + it * 256;
            int row = idx >> 3, seg = idx & 7;
            *(uint4*)&kbuf[row * 72 + seg * 8] =
                *(const uint4*)(kbase + (size_t)(ch * 128 + row) * 64 + seg * 8);
        }
        __syncthreads();
        float4 cacc[2][2];
        #pragma unroll
        for (int mt = 0; mt < 2; mt++)
            #pragma unroll
            for (int nt = 0; nt < 2; nt++) cacc[mt][nt] = make_float4(0.f,0.f,0.f,0.f);
        mma_chunk(qut, kbuf, w, gid, tig, cacc);
        #pragma unroll
        for (int mt = 0; mt < 2; mt++) {
            #pragma unroll
            for (int nt = 0; nt < 2; nt++) {
                float4 c = cacc[mt][nt];
                int ii = mt * 16 + gid;
                int col = ch * 128 + w * 16 + nt * 8 + tig * 2;
                sc[ii * SC_STR + col]           += c.x;
                sc[ii * SC_STR + col + 1]       += c.y;
                sc[(ii + 8) * SC_STR + col]     += c.z;
                sc[(ii + 8) * SC_STR + col + 1] += c.w;
            }
        }
    }
    __syncthreads();

    // ---- Phase C: softmax (scale 1/8 inside exp) ----
    #pragma unroll
    for (int rr = 0; rr < 4; rr++) {
        int row = w * 4 + rr;
        float* rp = sc + row * SC_STR;
        float4 vv[8];
        float mx = -1e30f;
        #pragma unroll
        for (int g = 0; g < 8; g++) {
            vv[g] = *(const float4*)&rp[g * 128 + l * 4];
            mx = fmaxf(mx, fmaxf(fmaxf(vv[g].x, vv[g].y), fmaxf(vv[g].z, vv[g].w)));
        }
        #pragma unroll
        for (int o = 16; o; o >>= 1) mx = fmaxf(mx, __shfl_xor_sync(0xffffffffu, mx, o));
        float sum = 0.f;
        #pragma unroll
        for (int g = 0; g < 8; g++) {
            vv[g].x = __expf((vv[g].x - mx) * 0.125f);
            vv[g].y = __expf((vv[g].y - mx) * 0.125f);
            vv[g].z = __expf((vv[g].z - mx) * 0.125f);
            vv[g].w = __expf((vv[g].w - mx) * 0.125f);
            sum += vv[g].x + vv[g].y + vv[g].z + vv[g].w;
        }
        #pragma unroll
        for (int o = 16; o; o >>= 1) sum += __shfl_xor_sync(0xffffffffu, sum, o);
        float inv = 1.0f / sum;
        #pragma unroll
        for (int g = 0; g < 8; g++) {
            vv[g].x *= inv; vv[g].y *= inv; vv[g].z *= inv; vv[g].w *= inv;
            *(float4*)&rp[g * 128 + l * 4] = vv[g];
        }
    }

    // ---- Phase D: O = attn @ V (bf16 mma), k split across warps ----
    bf16* Vt = kbuf;                                  // [64][136]
    float4 oacc[2][8];
    #pragma unroll
    for (int mt = 0; mt < 2; mt++)
        #pragma unroll
        for (int nt = 0; nt < 8; nt++) oacc[mt][nt] = make_float4(0.f,0.f,0.f,0.f);

    #pragma unroll 1
    for (int ch = 0; ch < 8; ch++) {
        __syncthreads();
        #pragma unroll
        for (int it = 0; it < 4; it++) {
            int idx = tid + it * 256;
            int d = idx >> 4, seg = idx & 15;
            *(uint4*)&Vt[d * 136 + seg * 8] =
                *(const uint4*)(vbase + (size_t)d * 1024 + ch * 128 + seg * 8);
        }
        __syncthreads();
        int kb = ch * 128 + w * 16 + 2 * tig;
        unsigned a[2][4];
        #pragma unroll
        for (int mt = 0; mt < 2; mt++) {
            int r = mt * 16 + gid;
            const float* s0 = sc + r * SC_STR + kb;
            const float* s1 = s0 + 8 * SC_STR;
            float2 u;
            u = *(const float2*)s0;       a[mt][0] = pack_bf2(u.x, u.y);
            u = *(const float2*)s1;       a[mt][1] = pack_bf2(u.x, u.y);
            u = *(const float2*)(s0 + 8); a[mt][2] = pack_bf2(u.x, u.y);
            u = *(const float2*)(s1 + 8); a[mt][3] = pack_bf2(u.x, u.y);
        }
        #pragma unroll
        for (int nt = 0; nt < 8; nt++) {
            const bf16* br = Vt + (nt * 8 + gid) * 136 + w * 16 + 2 * tig;
            unsigned b0 = *(const unsigned*)br;
            unsigned b1 = *(const unsigned*)(br + 8);
            mma16(oacc[0][nt], a[0][0], a[0][1], a[0][2], a[0][3], b0, b1);
            mma16(oacc[1][nt], a[1][0], a[1][1], a[1][2], a[1][3], b0, b1);
        }
    }

    // per-warp partials -> sc overlay (probs dead), then cross-warp reduce
    __syncthreads();
    {
        float* pb = sc + w * 2176;
        #pragma unroll
        for (int mt = 0; mt < 2; mt++) {
            #pragma unroll
            for (int nt = 0; nt < 8; nt++) {
                float4 c = oacc[mt][nt];
                int r = mt * 16 + gid;
                int cc = nt * 8 + tig * 2;
                pb[r * 68 + cc]           = c.x;
                pb[r * 68 + cc + 1]       = c.y;
                pb[(r + 8) * 68 + cc]     = c.z;
                pb[(r + 8) * 68 + cc + 1] = c.w;
            }
        }
    }
    __syncthreads();
    #pragma unroll
    for (int rep = 0; rep < 2; rep++) {
        int e = tid + rep * 256;
        int row = e >> 4, d4 = (e & 15) * 4;
        float4 s = make_float4(0.f, 0.f, 0.f, 0.f);
        #pragma unroll
        for (int ww = 0; ww < 8; ww++) {
            float4 p4 = *(const float4*)&sc[ww * 2176 + row * 68 + d4];
            s.x += p4.x; s.y += p4.y; s.z += p4.z; s.w += p4.w;
        }
        uint2 o2 = make_uint2(pack_bf2(s.x, s.y), pack_bf2(s.z, s.w));
        *(uint2*)(ao + (size_t)(b * 1024 + i0 + row) * 512 + h * 64 + d4) = o2;
    }
}

// ============================ launch ============================
extern "C" void kernel_launch(void* const* d_in, const int* in_sizes, int n_in,
                              void* d_out, int out_size)
{
    const float* x       = (const float*)d_in[0];
    const float* pos_emb = (const float*)d_in[1];
    const float* ln_w    = (const float*)d_in[2];
    const float* ln_b    = (const float*)d_in[3];
    const float* Wq      = (const float*)d_in[4];
    const float* bq      = (const float*)d_in[5];
    const float* Wk      = (const float*)d_in[6];
    const float* bk      = (const float*)d_in[7];
    const float* Wv      = (const float*)d_in[8];
    const float* bv      = (const float*)d_in[9];
    const float* Wo      = (const float*)d_in[10];
    const float* bo      = (const float*)d_in[11];
    const float* Wp      = (const float*)d_in[12];
    const float* pbu     = (const float*)d_in[13];
    const float* pbv     = (const float*)d_in[14];
    float* out = (float*)d_out;

    bf16 *hp, *qp, *kp, *vp, *pp, *aop;
    cudaGetSymbolAddress((void**)&hp,  g_h);
    cudaGetSymbolAddress((void**)&qp,  g_q);
    cudaGetSymbolAddress((void**)&kp,  g_k);
    cudaGetSymbolAddress((void**)&vp,  g_v);
    cudaGetSymbolAddress((void**)&pp,  g_p);
    cudaGetSymbolAddress((void**)&aop, g_ao);

    cudaFuncSetAttribute(attn_kernel, cudaFuncAttributeMaxDynamicSharedMemorySize, ASM_B);

    ln_kernel<<<MTOK, 128>>>(x, ln_w, ln_b, hp);

    gemm_kernel<<<dim3(4, 64), 256>>>(hp, MTOK, 1, Wq, bq, nullptr, qp, 0);
    gemm_kernel<<<dim3(4, 64), 256>>>(hp, MTOK, 1, Wk, bk, nullptr, kp, 0);
    gemm_kernel<<<dim3(4, 64), 256>>>(hp, MTOK, 1, Wv, bv, nullptr, vp, 5);
    gemm_kernel<<<dim3(4, 16), 256>>>(pos_emb, CP, 0, Wp, nullptr, nullptr, pp, 3);

    attn_kernel<<<CB * CH * (CS / 32), 256, ASM_B>>>(pbu, pbv, aop);

    gemm_kernel<<<dim3(4, 64), 256>>>(aop, MTOK, 1, Wo, bo, x, out, 4);
}